// round 6
// baseline (speedup 1.0000x reference)
#include <cuda_runtime.h>
#include <cuda_fp16.h>
#include <cstdint>
#include <math_constants.h>

// ---------------------------------------------------------------------------
// GAT, 3 layers, N=4096, F_IN=256, HID=256, OUT=128, HEADS=4.
// Round 6: scan-free CSR build (lane-owns-segment, smem uint8 buffers, one
// warp scan per row); fp16 MMA GEMM w/ fused scores; float4 st gathers.
// ---------------------------------------------------------------------------

#define GN    4096
#define HEADS 4
#define PAD   128
#define BM    64
#define BN    128
#define BK    32
#define LSTRIDE 132   // bank-padded per-lane buffer stride (bytes)

__device__ __half g_xh [GN * 256];
__device__ __half g_W0h[256 * 256];
__device__ __half g_W1h[256 * 256];
__device__ __half g_W2h[256 * 512];
__device__ __half g_WhH[GN * 512];
__device__ __half g_hH [GN * 256];
__device__ float  g_st [GN * 8];      // [n][0..3]=s per head, [n][4..7]=t per head
__device__ int    g_cnt[GN];
__device__ int    g_col_idx[GN * PAD];
__device__ int    g_byte_mode;

// ---------------------------------------------------------------------------
// Adjacency dtype detection (64KB scan).
// ---------------------------------------------------------------------------
__global__ void detect_kernel(const unsigned char* __restrict__ adj) {
    __shared__ int s_mis, s_b0;
    if (threadIdx.x == 0) { s_mis = 0; s_b0 = 0; }
    __syncthreads();
    int mis = 0, b0 = 0;
    for (int off = threadIdx.x; off < (1 << 16); off += blockDim.x) {
        unsigned char v = adj[off];
        if (v) { if (off & 3) mis++; else b0++; }
    }
    if (mis) atomicAdd(&s_mis, mis);
    if (b0)  atomicAdd(&s_b0, b0);
    __syncthreads();
    if (threadIdx.x == 0) g_byte_mode = (s_mis > 0 && s_b0 > 0) ? 1 : 0;
}

// ---------------------------------------------------------------------------
// Scan-free CSR build. Warp per row; lane L owns columns [L*128,(L+1)*128).
// Each lane streams its segment (independent loads, no cross-lane deps),
// buffering local offsets as uint8 in padded smem. One warp scan at the end;
// concatenated lanes give globally ascending column order (same as before).
// ---------------------------------------------------------------------------
__device__ __forceinline__ int warp_excl_scan(int v, int lane, int& tot) {
    int p = v;
    #pragma unroll
    for (int o = 1; o < 32; o <<= 1) {
        int x = __shfl_up_sync(0xffffffffu, p, o);
        if (lane >= o) p += x;
    }
    tot = __shfl_sync(0xffffffffu, p, 31);
    return p - v;
}

__global__ __launch_bounds__(256) void csr_build(const void* __restrict__ adj) {
    __shared__ uint8_t lbuf[8][32][LSTRIDE];
    int warp = (blockIdx.x * blockDim.x + threadIdx.x) >> 5;
    if (warp >= GN) return;
    int lane = threadIdx.x & 31;
    uint8_t* mybuf = lbuf[(threadIdx.x >> 5)][lane];
    int r = warp;
    int cnt = 0;

    if (!g_byte_mode) {
        // word mode: lane segment = 128 words = 32 uint4
        const uint4* p = (const uint4*)adj + (size_t)r * 1024 + lane * 32;
        #pragma unroll 4
        for (int it = 0; it < 32; it++) {
            uint4 v = p[it];
            if (v.x) mybuf[cnt++] = (uint8_t)(it * 4 + 0);
            if (v.y) mybuf[cnt++] = (uint8_t)(it * 4 + 1);
            if (v.z) mybuf[cnt++] = (uint8_t)(it * 4 + 2);
            if (v.w) mybuf[cnt++] = (uint8_t)(it * 4 + 3);
        }
    } else {
        // byte mode: lane segment = 128 bytes = 8 uint4
        const uint4* p = (const uint4*)adj + (size_t)r * 256 + lane * 8;
        #pragma unroll
        for (int it = 0; it < 8; it++) {
            uint4 v = p[it];
            unsigned w[4] = {v.x, v.y, v.z, v.w};
            #pragma unroll
            for (int q = 0; q < 4; q++)
                #pragma unroll
                for (int b = 0; b < 4; b++)
                    if ((w[q] >> (8 * b)) & 0xFFu)
                        mybuf[cnt++] = (uint8_t)(it * 16 + q * 4 + b);
        }
    }

    int tot;
    int excl = warp_excl_scan(cnt, lane, tot);
    int base = r * PAD;
    int c0 = lane * 128;
    for (int k = 0; k < cnt; k++) {
        int pos = excl + k;
        if (pos < PAD) g_col_idx[base + pos] = c0 + mybuf[k];
    }
    if (lane == 0) g_cnt[r] = (tot < PAD) ? tot : PAD;
}

// ---------------------------------------------------------------------------
// Prep: x -> fp16, W0/W1/W2 [H][F][D] fp32 -> [F][H*D] fp16.
// ---------------------------------------------------------------------------
__global__ __launch_bounds__(256) void prep(
    const float* __restrict__ x,  const float* __restrict__ W0,
    const float* __restrict__ W1, const float* __restrict__ W2,
    __half* __restrict__ xh, __half* __restrict__ w0,
    __half* __restrict__ w1, __half* __restrict__ w2)
{
    int idx = blockIdx.x * 256 + threadIdx.x;
    const int NX4 = GN * 256 / 4;
    if (idx < NX4) {
        float4 v = ((const float4*)x)[idx];
        ((__half2*)xh)[2 * idx]     = __floats2half2_rn(v.x, v.y);
        ((__half2*)xh)[2 * idx + 1] = __floats2half2_rn(v.z, v.w);
        return;
    }
    int i0 = idx - NX4;
    if (i0 < 65536) {
        int h = i0 >> 14, rem = i0 & 16383, f = rem >> 6, d = rem & 63;
        w0[f * 256 + h * 64 + d] = __float2half(W0[i0]);
        return;
    }
    int i1 = i0 - 65536;
    if (i1 < 65536) {
        int h = i1 >> 14, rem = i1 & 16383, f = rem >> 6, d = rem & 63;
        w1[f * 256 + h * 64 + d] = __float2half(W1[i1]);
        return;
    }
    int i2 = i1 - 65536;
    if (i2 < 131072) {
        int h = i2 >> 15, rem = i2 & 32767, f = rem >> 7, d = rem & 127;
        w2[f * 512 + h * 128 + d] = __float2half(W2[i2]);
    }
}

// ---------------------------------------------------------------------------
// GEMM + fused attention scores (interleaved st output).
// ---------------------------------------------------------------------------
__device__ __forceinline__ uint32_t smem_u32(const void* p) {
    return (uint32_t)__cvta_generic_to_shared(p);
}

__global__ __launch_bounds__(256) void gemm_fused(
    const __half* __restrict__ A, const __half* __restrict__ B,
    __half* __restrict__ C, const float* __restrict__ a_src,
    const float* __restrict__ a_dst, float* __restrict__ st,
    int Kin, int Kout, int D)
{
    __shared__ __align__(16) __half As[2][BM][BK + 8];
    __shared__ __align__(16) __half Bs[2][BK][BN + 8];
    __shared__ float s_sm[4][BM], t_sm[4][BM];
    __shared__ float a_s[BN], a_d[BN];

    int tid  = threadIdx.x;
    int warp = tid >> 5, lane = tid & 31;
    int wm = warp >> 2;
    int wn = warp & 3;
    int row0 = blockIdx.y * BM;
    int col0 = blockIdx.x * BN;

    if (tid < BN) { a_s[tid] = a_src[col0 + tid]; a_d[tid] = a_dst[col0 + tid]; }

    float acc[2][4][4] = {};
    int ar = tid >> 2, ac = (tid & 3) * 8;

    #define LOAD_STAGE(stg, k0)                                                \
    {                                                                          \
        uint32_t da = smem_u32(&As[stg][ar][ac]);                              \
        asm volatile("cp.async.cg.shared.global [%0], [%1], 16;"               \
                     :: "r"(da), "l"(A + (size_t)(row0 + ar) * Kin + (k0) + ac)); \
        _Pragma("unroll")                                                      \
        for (int ss = 0; ss < 2; ss++) {                                       \
            int seg = tid + ss * 256;                                          \
            int br = seg >> 4, bc = (seg & 15) * 8;                            \
            uint32_t db = smem_u32(&Bs[stg][br][bc]);                          \
            asm volatile("cp.async.cg.shared.global [%0], [%1], 16;"           \
                         :: "r"(db), "l"(B + (size_t)((k0) + br) * Kout + col0 + bc)); \
        }                                                                      \
        asm volatile("cp.async.commit_group;");                                \
    }

    int KT = Kin / BK;
    LOAD_STAGE(0, 0);

    for (int kt = 0; kt < KT; kt++) {
        int cur = kt & 1;
        if (kt + 1 < KT) {
            LOAD_STAGE(cur ^ 1, (kt + 1) * BK);
            asm volatile("cp.async.wait_group 1;");
        } else {
            asm volatile("cp.async.wait_group 0;");
        }
        __syncthreads();

        #pragma unroll
        for (int kk = 0; kk < 2; kk++) {
            uint32_t afr[2][4];
            #pragma unroll
            for (int mt = 0; mt < 2; mt++) {
                int r = wm * 32 + mt * 16 + (lane & 15);
                int c = kk * 16 + (lane >> 4) * 8;
                uint32_t addr = smem_u32(&As[cur][r][c]);
                asm volatile(
                    "ldmatrix.sync.aligned.m8n8.x4.shared.b16 {%0,%1,%2,%3}, [%4];"
                    : "=r"(afr[mt][0]), "=r"(afr[mt][1]),
                      "=r"(afr[mt][2]), "=r"(afr[mt][3]) : "r"(addr));
            }
            uint32_t bfr[4][2];
            #pragma unroll
            for (int p = 0; p < 2; p++) {
                int r = kk * 16 + (lane & 15);
                int c = wn * 32 + p * 16 + (lane >> 4) * 8;
                uint32_t addr = smem_u32(&Bs[cur][r][c]);
                uint32_t r0, r1, r2, r3;
                asm volatile(
                    "ldmatrix.sync.aligned.m8n8.x4.trans.shared.b16 {%0,%1,%2,%3}, [%4];"
                    : "=r"(r0), "=r"(r1), "=r"(r2), "=r"(r3) : "r"(addr));
                bfr[p * 2][0] = r0;     bfr[p * 2][1] = r1;
                bfr[p * 2 + 1][0] = r2; bfr[p * 2 + 1][1] = r3;
            }
            #pragma unroll
            for (int mt = 0; mt < 2; mt++)
                #pragma unroll
                for (int nt = 0; nt < 4; nt++) {
                    asm volatile(
                        "mma.sync.aligned.m16n8k16.row.col.f32.f16.f16.f32 "
                        "{%0,%1,%2,%3}, {%4,%5,%6,%7}, {%8,%9}, {%0,%1,%2,%3};"
                        : "+f"(acc[mt][nt][0]), "+f"(acc[mt][nt][1]),
                          "+f"(acc[mt][nt][2]), "+f"(acc[mt][nt][3])
                        : "r"(afr[mt][0]), "r"(afr[mt][1]),
                          "r"(afr[mt][2]), "r"(afr[mt][3]),
                          "r"(bfr[nt][0]), "r"(bfr[nt][1]));
                }
        }
        __syncthreads();
    }
    #undef LOAD_STAGE

    int g = lane >> 2, t4 = lane & 3;
    float sp[2][2] = {}, tp[2][2] = {};
    #pragma unroll
    for (int mt = 0; mt < 2; mt++)
        #pragma unroll
        for (int nt = 0; nt < 4; nt++) {
            int cl = wn * 32 + nt * 8 + t4 * 2;
            int r  = row0 + wm * 32 + mt * 16;
            int c  = col0 + cl;
            __half2 lo = __floats2half2_rn(acc[mt][nt][0], acc[mt][nt][1]);
            __half2 hi = __floats2half2_rn(acc[mt][nt][2], acc[mt][nt][3]);
            *(__half2*)&C[(size_t)(r + g)     * Kout + c] = lo;
            *(__half2*)&C[(size_t)(r + g + 8) * Kout + c] = hi;
            float s0 = a_s[cl], s1 = a_s[cl + 1];
            float d0 = a_d[cl], d1 = a_d[cl + 1];
            sp[mt][0] += acc[mt][nt][0] * s0 + acc[mt][nt][1] * s1;
            sp[mt][1] += acc[mt][nt][2] * s0 + acc[mt][nt][3] * s1;
            tp[mt][0] += acc[mt][nt][0] * d0 + acc[mt][nt][1] * d1;
            tp[mt][1] += acc[mt][nt][2] * d0 + acc[mt][nt][3] * d1;
        }
    #pragma unroll
    for (int o = 1; o <= 2; o <<= 1)
        #pragma unroll
        for (int mt = 0; mt < 2; mt++) {
            sp[mt][0] += __shfl_xor_sync(0xffffffffu, sp[mt][0], o);
            sp[mt][1] += __shfl_xor_sync(0xffffffffu, sp[mt][1], o);
            tp[mt][0] += __shfl_xor_sync(0xffffffffu, tp[mt][0], o);
            tp[mt][1] += __shfl_xor_sync(0xffffffffu, tp[mt][1], o);
        }
    if (t4 == 0)
        #pragma unroll
        for (int mt = 0; mt < 2; mt++) {
            int r = wm * 32 + mt * 16 + g;
            s_sm[wn][r]     = sp[mt][0];  s_sm[wn][r + 8] = sp[mt][1];
            t_sm[wn][r]     = tp[mt][0];  t_sm[wn][r + 8] = tp[mt][1];
        }
    __syncthreads();
    if (tid < BM) {
        int r = row0 + tid;
        if (D == 64) {
            int h0 = col0 >> 6;                 // 0 or 2
            st[r * 8 + h0]         = s_sm[0][tid] + s_sm[1][tid];
            st[r * 8 + h0 + 1]     = s_sm[2][tid] + s_sm[3][tid];
            st[r * 8 + 4 + h0]     = t_sm[0][tid] + t_sm[1][tid];
            st[r * 8 + 4 + h0 + 1] = t_sm[2][tid] + t_sm[3][tid];
        } else {
            int h = col0 >> 7;                  // 0..3
            st[r * 8 + h]     = s_sm[0][tid] + s_sm[1][tid] + s_sm[2][tid] + s_sm[3][tid];
            st[r * 8 + 4 + h] = t_sm[0][tid] + t_sm[1][tid] + t_sm[2][tid] + t_sm[3][tid];
        }
    }
}

// ---------------------------------------------------------------------------
// Sparse softmax + aggregation. float4 score gathers via interleaved st.
// ---------------------------------------------------------------------------
__global__ __launch_bounds__(256) void agg_kernel(
    const __half* __restrict__ WhH, const float* __restrict__ st,
    void* __restrict__ outp, int D, int meanMode)
{
    int K   = HEADS * D;
    int CPS = K >> 3;
    int G   = 256 / CPS;
    __shared__ int   sidx[PAD];
    __shared__ float sw[HEADS][PAD];
    __shared__ float sz[HEADS];
    __shared__ float4 ssrc4;
    __shared__ float buf[2048];

    int i   = blockIdx.x;
    int tid = threadIdx.x;
    int sl  = tid % CPS;
    int g   = tid / CPS;
    int c8  = sl * 8;
    int h   = c8 / D;

    if (tid == 0) ssrc4 = *(const float4*)&st[(size_t)i * 8];
    int cnt = g_cnt[i];
    if (tid < cnt) sidx[tid] = g_col_idx[i * PAD + tid];
    __syncthreads();

    if (tid < cnt) {
        int j = sidx[tid];
        float4 tv = *(const float4*)&st[(size_t)j * 8 + 4];
        float z0 = ssrc4.x + tv.x, z1 = ssrc4.y + tv.y;
        float z2 = ssrc4.z + tv.z, z3 = ssrc4.w + tv.w;
        sw[0][tid] = (z0 > 0.f) ? z0 : 0.2f * z0;
        sw[1][tid] = (z1 > 0.f) ? z1 : 0.2f * z1;
        sw[2][tid] = (z2 > 0.f) ? z2 : 0.2f * z2;
        sw[3][tid] = (z3 > 0.f) ? z3 : 0.2f * z3;
    }
    __syncthreads();

    {
        int wid = tid >> 5, lane = tid & 31;
        if (wid < HEADS) {
            int hh = wid;
            float mx = -CUDART_INF_F;
            for (int k = lane; k < cnt; k += 32) mx = fmaxf(mx, sw[hh][k]);
            #pragma unroll
            for (int o = 16; o; o >>= 1)
                mx = fmaxf(mx, __shfl_xor_sync(0xffffffffu, mx, o));
            float lz = 0.f;
            for (int k = lane; k < cnt; k += 32) {
                float w = __expf(sw[hh][k] - mx);
                sw[hh][k] = w;
                lz += w;
            }
            #pragma unroll
            for (int o = 16; o; o >>= 1) lz += __shfl_xor_sync(0xffffffffu, lz, o);
            if (lane == 0) sz[hh] = lz;
        }
    }
    __syncthreads();

    float acc[8] = {};
    const float* swh = sw[h];
    #pragma unroll 4
    for (int k = g; k < cnt; k += G) {
        float w = swh[k];
        uint4 v = *(const uint4*)&WhH[(size_t)sidx[k] * K + c8];
        float2 p0 = __half22float2(*(__half2*)&v.x);
        float2 p1 = __half22float2(*(__half2*)&v.y);
        float2 p2 = __half22float2(*(__half2*)&v.z);
        float2 p3 = __half22float2(*(__half2*)&v.w);
        acc[0] += w * p0.x; acc[1] += w * p0.y;
        acc[2] += w * p1.x; acc[3] += w * p1.y;
        acc[4] += w * p2.x; acc[5] += w * p2.y;
        acc[6] += w * p3.x; acc[7] += w * p3.y;
    }
    float* bg = buf + g * K + c8;
    #pragma unroll
    for (int q = 0; q < 8; q++) bg[q] = acc[q];
    __syncthreads();

    if (!meanMode) {
        __half* out = (__half*)outp;
        int c = tid;
        float v = 0.f;
        for (int gg = 0; gg < G; gg++) v += buf[gg * K + c];
        v /= sz[c / D];
        v = (v > 0.f) ? v : (__expf(v) - 1.f);
        out[(size_t)i * K + c] = __float2half(v);
    } else {
        float* out = (float*)outp;
        if (tid < D) {
            float v = 0.f;
            #pragma unroll
            for (int hh = 0; hh < HEADS; hh++) {
                float hv = 0.f;
                for (int gg = 0; gg < G; gg++) hv += buf[gg * K + hh * D + tid];
                v += hv / sz[hh];
            }
            out[(size_t)i * D + tid] = 0.25f * v;
        }
    }
}

// ---------------------------------------------------------------------------
extern "C" void kernel_launch(void* const* d_in, const int* in_sizes, int n_in,
                              void* d_out, int out_size)
{
    const float* x   = (const float*)d_in[0];
    const void*  adj =               d_in[1];
    const float* W0  = (const float*)d_in[2];
    const float* a0s = (const float*)d_in[3];
    const float* a0d = (const float*)d_in[4];
    const float* W1  = (const float*)d_in[5];
    const float* a1s = (const float*)d_in[6];
    const float* a1d = (const float*)d_in[7];
    const float* W2  = (const float*)d_in[8];
    const float* a2s = (const float*)d_in[9];
    const float* a2d = (const float*)d_in[10];
    float* out = (float*)d_out;

    __half *pxh, *pW0, *pW1, *pW2, *pWhH, *phH;
    float  *pst;
    cudaGetSymbolAddress((void**)&pxh,  g_xh);
    cudaGetSymbolAddress((void**)&pW0,  g_W0h);
    cudaGetSymbolAddress((void**)&pW1,  g_W1h);
    cudaGetSymbolAddress((void**)&pW2,  g_W2h);
    cudaGetSymbolAddress((void**)&pWhH, g_WhH);
    cudaGetSymbolAddress((void**)&phH,  g_hH);
    cudaGetSymbolAddress((void**)&pst,  g_st);

    static cudaStream_t sB = 0;
    static cudaEvent_t  eFork = 0, eJoin = 0;
    if (!sB) {
        cudaStreamCreateWithFlags(&sB, cudaStreamNonBlocking);
        cudaEventCreateWithFlags(&eFork, cudaEventDisableTiming);
        cudaEventCreateWithFlags(&eJoin, cudaEventDisableTiming);
    }

    cudaEventRecord(eFork, 0);
    cudaStreamWaitEvent(sB, eFork, 0);

    prep<<<2048, 256, 0, sB>>>(x, W0, W1, W2, pxh, pW0, pW1, pW2);
    gemm_fused<<<dim3(2, GN / BM), 256, 0, sB>>>(pxh, pW0, pWhH, a0s, a0d,
                                                 pst, 256, 256, 64);
    cudaEventRecord(eJoin, sB);

    detect_kernel<<<1, 256>>>((const unsigned char*)adj);
    csr_build<<<GN / 8, 256>>>(adj);
    cudaStreamWaitEvent(0, eJoin, 0);

    agg_kernel<<<GN, 256>>>(pWhH, pst, phH, 64, 0);

    gemm_fused<<<dim3(2, GN / BM), 256>>>(phH, pW1, pWhH, a1s, a1d,
                                          pst, 256, 256, 64);
    agg_kernel<<<GN, 256>>>(pWhH, pst, phH, 64, 0);

    gemm_fused<<<dim3(4, GN / BM), 256>>>(phH, pW2, pWhH, a2s, a2d,
                                          pst, 256, 512, 128);
    agg_kernel<<<GN, 256>>>(pWhH, pst, out, 128, 1);
}

// round 7
// speedup vs baseline: 1.0804x; 1.0804x over previous
#include <cuda_runtime.h>
#include <cuda_fp16.h>
#include <cstdint>
#include <math_constants.h>

// ---------------------------------------------------------------------------
// GAT, 3 layers, N=4096, F_IN=256, HID=256, OUT=128, HEADS=4.
// Round 7: round-5 CSR structure (coalesced lane-strided uint4, MLP=4) with
// ballot-based ranking (no shfl-scan chain); fp16 MMA GEMM w/ fused scores.
// ---------------------------------------------------------------------------

#define GN    4096
#define HEADS 4
#define PAD   128
#define BM    64
#define BN    128
#define BK    32

__device__ __half g_xh [GN * 256];
__device__ __half g_W0h[256 * 256];
__device__ __half g_W1h[256 * 256];
__device__ __half g_W2h[256 * 512];
__device__ __half g_WhH[GN * 512];
__device__ __half g_hH [GN * 256];
__device__ float  g_st [GN * 8];      // [n][0..3]=s per head, [n][4..7]=t per head
__device__ int    g_cnt[GN];
__device__ int    g_col_idx[GN * PAD];
__device__ int    g_byte_mode;

// ---------------------------------------------------------------------------
// Adjacency dtype detection (64KB scan).
// ---------------------------------------------------------------------------
__global__ void detect_kernel(const unsigned char* __restrict__ adj) {
    __shared__ int s_mis, s_b0;
    if (threadIdx.x == 0) { s_mis = 0; s_b0 = 0; }
    __syncthreads();
    int mis = 0, b0 = 0;
    for (int off = threadIdx.x; off < (1 << 16); off += blockDim.x) {
        unsigned char v = adj[off];
        if (v) { if (off & 3) mis++; else b0++; }
    }
    if (mis) atomicAdd(&s_mis, mis);
    if (b0)  atomicAdd(&s_b0, b0);
    __syncthreads();
    if (threadIdx.x == 0) g_byte_mode = (s_mis > 0 && s_b0 > 0) ? 1 : 0;
}

// ---------------------------------------------------------------------------
// CSR build: warp per row, lane-strided coalesced uint4 loads, 4-deep MLP
// batching, ballot-based per-iteration ranking (no scan chain).
// Column order: c = it*128 + lane*4 + q  (lane-major, ascending).
// ---------------------------------------------------------------------------
__device__ __forceinline__ int warp_excl_scan(int v, int lane, int& tot) {
    int p = v;
    #pragma unroll
    for (int o = 1; o < 32; o <<= 1) {
        int x = __shfl_up_sync(0xffffffffu, p, o);
        if (lane >= o) p += x;
    }
    tot = __shfl_sync(0xffffffffu, p, 31);
    return p - v;
}

__global__ __launch_bounds__(256) void csr_build(const void* __restrict__ adj) {
    int warp = (blockIdx.x * blockDim.x + threadIdx.x) >> 5;
    if (warp >= GN) return;
    int lane = threadIdx.x & 31;
    int r    = warp;
    int base = r * PAD;
    int total = 0;
    int lim = base + PAD;
    unsigned below = (1u << lane) - 1u;

    if (!g_byte_mode) {
        const uint4* p = (const uint4*)adj + (size_t)r * 1024;
        for (int ob = 0; ob < 32; ob += 4) {
            uint4 v[4];
            #pragma unroll
            for (int q = 0; q < 4; q++) v[q] = p[(ob + q) * 32 + lane];
            #pragma unroll
            for (int q = 0; q < 4; q++) {
                int it = ob + q;
                int b0 = (v[q].x != 0u), b1 = (v[q].y != 0u);
                int b2 = (v[q].z != 0u), b3 = (v[q].w != 0u);
                unsigned m0 = __ballot_sync(0xffffffffu, b0);
                unsigned m1 = __ballot_sync(0xffffffffu, b1);
                unsigned m2 = __ballot_sync(0xffffffffu, b2);
                unsigned m3 = __ballot_sync(0xffffffffu, b3);
                int pre = __popc(m0 & below) + __popc(m1 & below)
                        + __popc(m2 & below) + __popc(m3 & below);
                int pos = base + total + pre;
                int c0 = it * 128 + lane * 4;
                if (b0) { if (pos < lim) g_col_idx[pos] = c0 + 0; pos++; }
                if (b1) { if (pos < lim) g_col_idx[pos] = c0 + 1; pos++; }
                if (b2) { if (pos < lim) g_col_idx[pos] = c0 + 2; pos++; }
                if (b3) { if (pos < lim) g_col_idx[pos] = c0 + 3; pos++; }
                total += __popc(m0) + __popc(m1) + __popc(m2) + __popc(m3);
            }
        }
    } else {
        const uint4* p = (const uint4*)adj + (size_t)r * 256;
        for (int ob = 0; ob < 8; ob += 4) {
            uint4 v[4];
            #pragma unroll
            for (int q = 0; q < 4; q++) v[q] = p[(ob + q) * 32 + lane];
            #pragma unroll
            for (int q = 0; q < 4; q++) {
                int it = ob + q;
                unsigned w[4] = {v[q].x, v[q].y, v[q].z, v[q].w};
                int own = 0;
                #pragma unroll
                for (int u = 0; u < 4; u++)
                    #pragma unroll
                    for (int b = 0; b < 4; b++)
                        own += ((w[u] >> (8 * b)) & 0xFFu) ? 1 : 0;
                int tot;
                int excl = warp_excl_scan(own, lane, tot);
                int pos = base + total + excl;
                int c0 = it * 512 + lane * 16;
                #pragma unroll
                for (int u = 0; u < 4; u++)
                    #pragma unroll
                    for (int b = 0; b < 4; b++)
                        if ((w[u] >> (8 * b)) & 0xFFu) {
                            if (pos < lim) g_col_idx[pos] = c0 + u * 4 + b;
                            pos++;
                        }
                total += tot;
            }
        }
    }
    if (lane == 0) g_cnt[r] = (total < PAD) ? total : PAD;
}

// ---------------------------------------------------------------------------
// Prep: x -> fp16, W0/W1/W2 [H][F][D] fp32 -> [F][H*D] fp16.
// ---------------------------------------------------------------------------
__global__ __launch_bounds__(256) void prep(
    const float* __restrict__ x,  const float* __restrict__ W0,
    const float* __restrict__ W1, const float* __restrict__ W2,
    __half* __restrict__ xh, __half* __restrict__ w0,
    __half* __restrict__ w1, __half* __restrict__ w2)
{
    int idx = blockIdx.x * 256 + threadIdx.x;
    const int NX4 = GN * 256 / 4;
    if (idx < NX4) {
        float4 v = ((const float4*)x)[idx];
        ((__half2*)xh)[2 * idx]     = __floats2half2_rn(v.x, v.y);
        ((__half2*)xh)[2 * idx + 1] = __floats2half2_rn(v.z, v.w);
        return;
    }
    int i0 = idx - NX4;
    if (i0 < 65536) {
        int h = i0 >> 14, rem = i0 & 16383, f = rem >> 6, d = rem & 63;
        w0[f * 256 + h * 64 + d] = __float2half(W0[i0]);
        return;
    }
    int i1 = i0 - 65536;
    if (i1 < 65536) {
        int h = i1 >> 14, rem = i1 & 16383, f = rem >> 6, d = rem & 63;
        w1[f * 256 + h * 64 + d] = __float2half(W1[i1]);
        return;
    }
    int i2 = i1 - 65536;
    if (i2 < 131072) {
        int h = i2 >> 15, rem = i2 & 32767, f = rem >> 7, d = rem & 127;
        w2[f * 512 + h * 128 + d] = __float2half(W2[i2]);
    }
}

// ---------------------------------------------------------------------------
// GEMM + fused attention scores (interleaved st output).
// ---------------------------------------------------------------------------
__device__ __forceinline__ uint32_t smem_u32(const void* p) {
    return (uint32_t)__cvta_generic_to_shared(p);
}

__global__ __launch_bounds__(256) void gemm_fused(
    const __half* __restrict__ A, const __half* __restrict__ B,
    __half* __restrict__ C, const float* __restrict__ a_src,
    const float* __restrict__ a_dst, float* __restrict__ st,
    int Kin, int Kout, int D)
{
    __shared__ __align__(16) __half As[2][BM][BK + 8];
    __shared__ __align__(16) __half Bs[2][BK][BN + 8];
    __shared__ float s_sm[4][BM], t_sm[4][BM];
    __shared__ float a_s[BN], a_d[BN];

    int tid  = threadIdx.x;
    int warp = tid >> 5, lane = tid & 31;
    int wm = warp >> 2;
    int wn = warp & 3;
    int row0 = blockIdx.y * BM;
    int col0 = blockIdx.x * BN;

    if (tid < BN) { a_s[tid] = a_src[col0 + tid]; a_d[tid] = a_dst[col0 + tid]; }

    float acc[2][4][4] = {};
    int ar = tid >> 2, ac = (tid & 3) * 8;

    #define LOAD_STAGE(stg, k0)                                                \
    {                                                                          \
        uint32_t da = smem_u32(&As[stg][ar][ac]);                              \
        asm volatile("cp.async.cg.shared.global [%0], [%1], 16;"               \
                     :: "r"(da), "l"(A + (size_t)(row0 + ar) * Kin + (k0) + ac)); \
        _Pragma("unroll")                                                      \
        for (int ss = 0; ss < 2; ss++) {                                       \
            int seg = tid + ss * 256;                                          \
            int br = seg >> 4, bc = (seg & 15) * 8;                            \
            uint32_t db = smem_u32(&Bs[stg][br][bc]);                          \
            asm volatile("cp.async.cg.shared.global [%0], [%1], 16;"           \
                         :: "r"(db), "l"(B + (size_t)((k0) + br) * Kout + col0 + bc)); \
        }                                                                      \
        asm volatile("cp.async.commit_group;");                                \
    }

    int KT = Kin / BK;
    LOAD_STAGE(0, 0);

    for (int kt = 0; kt < KT; kt++) {
        int cur = kt & 1;
        if (kt + 1 < KT) {
            LOAD_STAGE(cur ^ 1, (kt + 1) * BK);
            asm volatile("cp.async.wait_group 1;");
        } else {
            asm volatile("cp.async.wait_group 0;");
        }
        __syncthreads();

        #pragma unroll
        for (int kk = 0; kk < 2; kk++) {
            uint32_t afr[2][4];
            #pragma unroll
            for (int mt = 0; mt < 2; mt++) {
                int r = wm * 32 + mt * 16 + (lane & 15);
                int c = kk * 16 + (lane >> 4) * 8;
                uint32_t addr = smem_u32(&As[cur][r][c]);
                asm volatile(
                    "ldmatrix.sync.aligned.m8n8.x4.shared.b16 {%0,%1,%2,%3}, [%4];"
                    : "=r"(afr[mt][0]), "=r"(afr[mt][1]),
                      "=r"(afr[mt][2]), "=r"(afr[mt][3]) : "r"(addr));
            }
            uint32_t bfr[4][2];
            #pragma unroll
            for (int p = 0; p < 2; p++) {
                int r = kk * 16 + (lane & 15);
                int c = wn * 32 + p * 16 + (lane >> 4) * 8;
                uint32_t addr = smem_u32(&Bs[cur][r][c]);
                uint32_t r0, r1, r2, r3;
                asm volatile(
                    "ldmatrix.sync.aligned.m8n8.x4.trans.shared.b16 {%0,%1,%2,%3}, [%4];"
                    : "=r"(r0), "=r"(r1), "=r"(r2), "=r"(r3) : "r"(addr));
                bfr[p * 2][0] = r0;     bfr[p * 2][1] = r1;
                bfr[p * 2 + 1][0] = r2; bfr[p * 2 + 1][1] = r3;
            }
            #pragma unroll
            for (int mt = 0; mt < 2; mt++)
                #pragma unroll
                for (int nt = 0; nt < 4; nt++) {
                    asm volatile(
                        "mma.sync.aligned.m16n8k16.row.col.f32.f16.f16.f32 "
                        "{%0,%1,%2,%3}, {%4,%5,%6,%7}, {%8,%9}, {%0,%1,%2,%3};"
                        : "+f"(acc[mt][nt][0]), "+f"(acc[mt][nt][1]),
                          "+f"(acc[mt][nt][2]), "+f"(acc[mt][nt][3])
                        : "r"(afr[mt][0]), "r"(afr[mt][1]),
                          "r"(afr[mt][2]), "r"(afr[mt][3]),
                          "r"(bfr[nt][0]), "r"(bfr[nt][1]));
                }
        }
        __syncthreads();
    }
    #undef LOAD_STAGE

    int g = lane >> 2, t4 = lane & 3;
    float sp[2][2] = {}, tp[2][2] = {};
    #pragma unroll
    for (int mt = 0; mt < 2; mt++)
        #pragma unroll
        for (int nt = 0; nt < 4; nt++) {
            int cl = wn * 32 + nt * 8 + t4 * 2;
            int r  = row0 + wm * 32 + mt * 16;
            int c  = col0 + cl;
            __half2 lo = __floats2half2_rn(acc[mt][nt][0], acc[mt][nt][1]);
            __half2 hi = __floats2half2_rn(acc[mt][nt][2], acc[mt][nt][3]);
            *(__half2*)&C[(size_t)(r + g)     * Kout + c] = lo;
            *(__half2*)&C[(size_t)(r + g + 8) * Kout + c] = hi;
            float s0 = a_s[cl], s1 = a_s[cl + 1];
            float d0 = a_d[cl], d1 = a_d[cl + 1];
            sp[mt][0] += acc[mt][nt][0] * s0 + acc[mt][nt][1] * s1;
            sp[mt][1] += acc[mt][nt][2] * s0 + acc[mt][nt][3] * s1;
            tp[mt][0] += acc[mt][nt][0] * d0 + acc[mt][nt][1] * d1;
            tp[mt][1] += acc[mt][nt][2] * d0 + acc[mt][nt][3] * d1;
        }
    #pragma unroll
    for (int o = 1; o <= 2; o <<= 1)
        #pragma unroll
        for (int mt = 0; mt < 2; mt++) {
            sp[mt][0] += __shfl_xor_sync(0xffffffffu, sp[mt][0], o);
            sp[mt][1] += __shfl_xor_sync(0xffffffffu, sp[mt][1], o);
            tp[mt][0] += __shfl_xor_sync(0xffffffffu, tp[mt][0], o);
            tp[mt][1] += __shfl_xor_sync(0xffffffffu, tp[mt][1], o);
        }
    if (t4 == 0)
        #pragma unroll
        for (int mt = 0; mt < 2; mt++) {
            int r = wm * 32 + mt * 16 + g;
            s_sm[wn][r]     = sp[mt][0];  s_sm[wn][r + 8] = sp[mt][1];
            t_sm[wn][r]     = tp[mt][0];  t_sm[wn][r + 8] = tp[mt][1];
        }
    __syncthreads();
    if (tid < BM) {
        int r = row0 + tid;
        if (D == 64) {
            int h0 = col0 >> 6;                 // 0 or 2
            st[r * 8 + h0]         = s_sm[0][tid] + s_sm[1][tid];
            st[r * 8 + h0 + 1]     = s_sm[2][tid] + s_sm[3][tid];
            st[r * 8 + 4 + h0]     = t_sm[0][tid] + t_sm[1][tid];
            st[r * 8 + 4 + h0 + 1] = t_sm[2][tid] + t_sm[3][tid];
        } else {
            int h = col0 >> 7;                  // 0..3
            st[r * 8 + h]     = s_sm[0][tid] + s_sm[1][tid] + s_sm[2][tid] + s_sm[3][tid];
            st[r * 8 + 4 + h] = t_sm[0][tid] + t_sm[1][tid] + t_sm[2][tid] + t_sm[3][tid];
        }
    }
}

// ---------------------------------------------------------------------------
// Sparse softmax + aggregation. float4 score gathers via interleaved st.
// ---------------------------------------------------------------------------
__global__ __launch_bounds__(256) void agg_kernel(
    const __half* __restrict__ WhH, const float* __restrict__ st,
    void* __restrict__ outp, int D, int meanMode)
{
    int K   = HEADS * D;
    int CPS = K >> 3;
    int G   = 256 / CPS;
    __shared__ int   sidx[PAD];
    __shared__ float sw[HEADS][PAD];
    __shared__ float sz[HEADS];
    __shared__ float4 ssrc4;
    __shared__ float buf[2048];

    int i   = blockIdx.x;
    int tid = threadIdx.x;
    int sl  = tid % CPS;
    int g   = tid / CPS;
    int c8  = sl * 8;
    int h   = c8 / D;

    if (tid == 0) ssrc4 = *(const float4*)&st[(size_t)i * 8];
    int cnt = g_cnt[i];
    if (tid < cnt) sidx[tid] = g_col_idx[i * PAD + tid];
    __syncthreads();

    if (tid < cnt) {
        int j = sidx[tid];
        float4 tv = *(const float4*)&st[(size_t)j * 8 + 4];
        float z0 = ssrc4.x + tv.x, z1 = ssrc4.y + tv.y;
        float z2 = ssrc4.z + tv.z, z3 = ssrc4.w + tv.w;
        sw[0][tid] = (z0 > 0.f) ? z0 : 0.2f * z0;
        sw[1][tid] = (z1 > 0.f) ? z1 : 0.2f * z1;
        sw[2][tid] = (z2 > 0.f) ? z2 : 0.2f * z2;
        sw[3][tid] = (z3 > 0.f) ? z3 : 0.2f * z3;
    }
    __syncthreads();

    {
        int wid = tid >> 5, lane = tid & 31;
        if (wid < HEADS) {
            int hh = wid;
            float mx = -CUDART_INF_F;
            for (int k = lane; k < cnt; k += 32) mx = fmaxf(mx, sw[hh][k]);
            #pragma unroll
            for (int o = 16; o; o >>= 1)
                mx = fmaxf(mx, __shfl_xor_sync(0xffffffffu, mx, o));
            float lz = 0.f;
            for (int k = lane; k < cnt; k += 32) {
                float w = __expf(sw[hh][k] - mx);
                sw[hh][k] = w;
                lz += w;
            }
            #pragma unroll
            for (int o = 16; o; o >>= 1) lz += __shfl_xor_sync(0xffffffffu, lz, o);
            if (lane == 0) sz[hh] = lz;
        }
    }
    __syncthreads();

    float acc[8] = {};
    const float* swh = sw[h];
    #pragma unroll 4
    for (int k = g; k < cnt; k += G) {
        float w = swh[k];
        uint4 v = *(const uint4*)&WhH[(size_t)sidx[k] * K + c8];
        float2 p0 = __half22float2(*(__half2*)&v.x);
        float2 p1 = __half22float2(*(__half2*)&v.y);
        float2 p2 = __half22float2(*(__half2*)&v.z);
        float2 p3 = __half22float2(*(__half2*)&v.w);
        acc[0] += w * p0.x; acc[1] += w * p0.y;
        acc[2] += w * p1.x; acc[3] += w * p1.y;
        acc[4] += w * p2.x; acc[5] += w * p2.y;
        acc[6] += w * p3.x; acc[7] += w * p3.y;
    }
    float* bg = buf + g * K + c8;
    #pragma unroll
    for (int q = 0; q < 8; q++) bg[q] = acc[q];
    __syncthreads();

    if (!meanMode) {
        __half* out = (__half*)outp;
        int c = tid;
        float v = 0.f;
        for (int gg = 0; gg < G; gg++) v += buf[gg * K + c];
        v /= sz[c / D];
        v = (v > 0.f) ? v : (__expf(v) - 1.f);
        out[(size_t)i * K + c] = __float2half(v);
    } else {
        float* out = (float*)outp;
        if (tid < D) {
            float v = 0.f;
            #pragma unroll
            for (int hh = 0; hh < HEADS; hh++) {
                float hv = 0.f;
                for (int gg = 0; gg < G; gg++) hv += buf[gg * K + hh * D + tid];
                v += hv / sz[hh];
            }
            out[(size_t)i * D + tid] = 0.25f * v;
        }
    }
}

// ---------------------------------------------------------------------------
extern "C" void kernel_launch(void* const* d_in, const int* in_sizes, int n_in,
                              void* d_out, int out_size)
{
    const float* x   = (const float*)d_in[0];
    const void*  adj =               d_in[1];
    const float* W0  = (const float*)d_in[2];
    const float* a0s = (const float*)d_in[3];
    const float* a0d = (const float*)d_in[4];
    const float* W1  = (const float*)d_in[5];
    const float* a1s = (const float*)d_in[6];
    const float* a1d = (const float*)d_in[7];
    const float* W2  = (const float*)d_in[8];
    const float* a2s = (const float*)d_in[9];
    const float* a2d = (const float*)d_in[10];
    float* out = (float*)d_out;

    __half *pxh, *pW0, *pW1, *pW2, *pWhH, *phH;
    float  *pst;
    cudaGetSymbolAddress((void**)&pxh,  g_xh);
    cudaGetSymbolAddress((void**)&pW0,  g_W0h);
    cudaGetSymbolAddress((void**)&pW1,  g_W1h);
    cudaGetSymbolAddress((void**)&pW2,  g_W2h);
    cudaGetSymbolAddress((void**)&pWhH, g_WhH);
    cudaGetSymbolAddress((void**)&phH,  g_hH);
    cudaGetSymbolAddress((void**)&pst,  g_st);

    static cudaStream_t sB = 0;
    static cudaEvent_t  eFork = 0, eJoin = 0;
    if (!sB) {
        cudaStreamCreateWithFlags(&sB, cudaStreamNonBlocking);
        cudaEventCreateWithFlags(&eFork, cudaEventDisableTiming);
        cudaEventCreateWithFlags(&eJoin, cudaEventDisableTiming);
    }

    cudaEventRecord(eFork, 0);
    cudaStreamWaitEvent(sB, eFork, 0);

    prep<<<2048, 256, 0, sB>>>(x, W0, W1, W2, pxh, pW0, pW1, pW2);
    gemm_fused<<<dim3(2, GN / BM), 256, 0, sB>>>(pxh, pW0, pWhH, a0s, a0d,
                                                 pst, 256, 256, 64);
    cudaEventRecord(eJoin, sB);

    detect_kernel<<<1, 256>>>((const unsigned char*)adj);
    csr_build<<<GN / 8, 256>>>(adj);
    cudaStreamWaitEvent(0, eJoin, 0);

    agg_kernel<<<GN, 256>>>(pWhH, pst, phH, 64, 0);

    gemm_fused<<<dim3(2, GN / BM), 256>>>(phH, pW1, pWhH, a1s, a1d,
                                          pst, 256, 256, 64);
    agg_kernel<<<GN, 256>>>(pWhH, pst, phH, 64, 0);

    gemm_fused<<<dim3(4, GN / BM), 256>>>(phH, pW2, pWhH, a2s, a2d,
                                          pst, 256, 512, 128);
    agg_kernel<<<GN, 256>>>(pWhH, pst, out, 128, 1);
}

// round 8
// speedup vs baseline: 1.2149x; 1.1245x over previous
#include <cuda_runtime.h>
#include <cuda_fp16.h>
#include <cstdint>
#include <math_constants.h>

// ---------------------------------------------------------------------------
// GAT, 3 layers, N=4096, F_IN=256, HID=256, OUT=128, HEADS=4.
// Round 8: barrier-free warp-per-(node,head) aggregation; ballot CSR;
// cp.async fp16 MMA GEMM with fused score epilogue; stream fork/join.
// ---------------------------------------------------------------------------

#define GN    4096
#define HEADS 4
#define PAD   128
#define BM    64
#define BN    128
#define BK    32

__device__ __half g_xh [GN * 256];
__device__ __half g_W0h[256 * 256];
__device__ __half g_W1h[256 * 256];
__device__ __half g_W2h[256 * 512];
__device__ __half g_WhH[GN * 512];
__device__ __half g_hH [GN * 256];
__device__ float  g_st [GN * 8];      // [n][0..3]=s per head, [n][4..7]=t per head
__device__ int    g_cnt[GN];
__device__ int    g_col_idx[GN * PAD];
__device__ int    g_byte_mode;

// ---------------------------------------------------------------------------
// Adjacency dtype detection (64KB scan).
// ---------------------------------------------------------------------------
__global__ void detect_kernel(const unsigned char* __restrict__ adj) {
    __shared__ int s_mis, s_b0;
    if (threadIdx.x == 0) { s_mis = 0; s_b0 = 0; }
    __syncthreads();
    int mis = 0, b0 = 0;
    for (int off = threadIdx.x; off < (1 << 16); off += blockDim.x) {
        unsigned char v = adj[off];
        if (v) { if (off & 3) mis++; else b0++; }
    }
    if (mis) atomicAdd(&s_mis, mis);
    if (b0)  atomicAdd(&s_b0, b0);
    __syncthreads();
    if (threadIdx.x == 0) g_byte_mode = (s_mis > 0 && s_b0 > 0) ? 1 : 0;
}

// ---------------------------------------------------------------------------
// CSR build: warp per row, coalesced lane-strided uint4, MLP=4, ballot rank.
// ---------------------------------------------------------------------------
__device__ __forceinline__ int warp_excl_scan(int v, int lane, int& tot) {
    int p = v;
    #pragma unroll
    for (int o = 1; o < 32; o <<= 1) {
        int x = __shfl_up_sync(0xffffffffu, p, o);
        if (lane >= o) p += x;
    }
    tot = __shfl_sync(0xffffffffu, p, 31);
    return p - v;
}

__global__ __launch_bounds__(256) void csr_build(const void* __restrict__ adj) {
    int warp = (blockIdx.x * blockDim.x + threadIdx.x) >> 5;
    if (warp >= GN) return;
    int lane = threadIdx.x & 31;
    int r    = warp;
    int base = r * PAD;
    int total = 0;
    int lim = base + PAD;
    unsigned below = (1u << lane) - 1u;

    if (!g_byte_mode) {
        const uint4* p = (const uint4*)adj + (size_t)r * 1024;
        for (int ob = 0; ob < 32; ob += 4) {
            uint4 v[4];
            #pragma unroll
            for (int q = 0; q < 4; q++) v[q] = p[(ob + q) * 32 + lane];
            #pragma unroll
            for (int q = 0; q < 4; q++) {
                int it = ob + q;
                int b0 = (v[q].x != 0u), b1 = (v[q].y != 0u);
                int b2 = (v[q].z != 0u), b3 = (v[q].w != 0u);
                unsigned m0 = __ballot_sync(0xffffffffu, b0);
                unsigned m1 = __ballot_sync(0xffffffffu, b1);
                unsigned m2 = __ballot_sync(0xffffffffu, b2);
                unsigned m3 = __ballot_sync(0xffffffffu, b3);
                int pre = __popc(m0 & below) + __popc(m1 & below)
                        + __popc(m2 & below) + __popc(m3 & below);
                int pos = base + total + pre;
                int c0 = it * 128 + lane * 4;
                if (b0) { if (pos < lim) g_col_idx[pos] = c0 + 0; pos++; }
                if (b1) { if (pos < lim) g_col_idx[pos] = c0 + 1; pos++; }
                if (b2) { if (pos < lim) g_col_idx[pos] = c0 + 2; pos++; }
                if (b3) { if (pos < lim) g_col_idx[pos] = c0 + 3; pos++; }
                total += __popc(m0) + __popc(m1) + __popc(m2) + __popc(m3);
            }
        }
    } else {
        const uint4* p = (const uint4*)adj + (size_t)r * 256;
        for (int ob = 0; ob < 8; ob += 4) {
            uint4 v[4];
            #pragma unroll
            for (int q = 0; q < 4; q++) v[q] = p[(ob + q) * 32 + lane];
            #pragma unroll
            for (int q = 0; q < 4; q++) {
                int it = ob + q;
                unsigned w[4] = {v[q].x, v[q].y, v[q].z, v[q].w};
                int own = 0;
                #pragma unroll
                for (int u = 0; u < 4; u++)
                    #pragma unroll
                    for (int b = 0; b < 4; b++)
                        own += ((w[u] >> (8 * b)) & 0xFFu) ? 1 : 0;
                int tot;
                int excl = warp_excl_scan(own, lane, tot);
                int pos = base + total + excl;
                int c0 = it * 512 + lane * 16;
                #pragma unroll
                for (int u = 0; u < 4; u++)
                    #pragma unroll
                    for (int b = 0; b < 4; b++)
                        if ((w[u] >> (8 * b)) & 0xFFu) {
                            if (pos < lim) g_col_idx[pos] = c0 + u * 4 + b;
                            pos++;
                        }
                total += tot;
            }
        }
    }
    if (lane == 0) g_cnt[r] = (total < PAD) ? total : PAD;
}

// ---------------------------------------------------------------------------
// Prep: x -> fp16, W0/W1/W2 [H][F][D] fp32 -> [F][H*D] fp16.
// ---------------------------------------------------------------------------
__global__ __launch_bounds__(256) void prep(
    const float* __restrict__ x,  const float* __restrict__ W0,
    const float* __restrict__ W1, const float* __restrict__ W2,
    __half* __restrict__ xh, __half* __restrict__ w0,
    __half* __restrict__ w1, __half* __restrict__ w2)
{
    int idx = blockIdx.x * 256 + threadIdx.x;
    const int NX4 = GN * 256 / 4;
    if (idx < NX4) {
        float4 v = ((const float4*)x)[idx];
        ((__half2*)xh)[2 * idx]     = __floats2half2_rn(v.x, v.y);
        ((__half2*)xh)[2 * idx + 1] = __floats2half2_rn(v.z, v.w);
        return;
    }
    int i0 = idx - NX4;
    if (i0 < 65536) {
        int h = i0 >> 14, rem = i0 & 16383, f = rem >> 6, d = rem & 63;
        w0[f * 256 + h * 64 + d] = __float2half(W0[i0]);
        return;
    }
    int i1 = i0 - 65536;
    if (i1 < 65536) {
        int h = i1 >> 14, rem = i1 & 16383, f = rem >> 6, d = rem & 63;
        w1[f * 256 + h * 64 + d] = __float2half(W1[i1]);
        return;
    }
    int i2 = i1 - 65536;
    if (i2 < 131072) {
        int h = i2 >> 15, rem = i2 & 32767, f = rem >> 7, d = rem & 127;
        w2[f * 512 + h * 128 + d] = __float2half(W2[i2]);
    }
}

// ---------------------------------------------------------------------------
// GEMM + fused attention scores (interleaved st output).
// ---------------------------------------------------------------------------
__device__ __forceinline__ uint32_t smem_u32(const void* p) {
    return (uint32_t)__cvta_generic_to_shared(p);
}

__global__ __launch_bounds__(256) void gemm_fused(
    const __half* __restrict__ A, const __half* __restrict__ B,
    __half* __restrict__ C, const float* __restrict__ a_src,
    const float* __restrict__ a_dst, float* __restrict__ st,
    int Kin, int Kout, int D)
{
    __shared__ __align__(16) __half As[2][BM][BK + 8];
    __shared__ __align__(16) __half Bs[2][BK][BN + 8];
    __shared__ float s_sm[4][BM], t_sm[4][BM];
    __shared__ float a_s[BN], a_d[BN];

    int tid  = threadIdx.x;
    int warp = tid >> 5, lane = tid & 31;
    int wm = warp >> 2;
    int wn = warp & 3;
    int row0 = blockIdx.y * BM;
    int col0 = blockIdx.x * BN;

    if (tid < BN) { a_s[tid] = a_src[col0 + tid]; a_d[tid] = a_dst[col0 + tid]; }

    float acc[2][4][4] = {};
    int ar = tid >> 2, ac = (tid & 3) * 8;

    #define LOAD_STAGE(stg, k0)                                                \
    {                                                                          \
        uint32_t da = smem_u32(&As[stg][ar][ac]);                              \
        asm volatile("cp.async.cg.shared.global [%0], [%1], 16;"               \
                     :: "r"(da), "l"(A + (size_t)(row0 + ar) * Kin + (k0) + ac)); \
        _Pragma("unroll")                                                      \
        for (int ss = 0; ss < 2; ss++) {                                       \
            int seg = tid + ss * 256;                                          \
            int br = seg >> 4, bc = (seg & 15) * 8;                            \
            uint32_t db = smem_u32(&Bs[stg][br][bc]);                          \
            asm volatile("cp.async.cg.shared.global [%0], [%1], 16;"           \
                         :: "r"(db), "l"(B + (size_t)((k0) + br) * Kout + col0 + bc)); \
        }                                                                      \
        asm volatile("cp.async.commit_group;");                                \
    }

    int KT = Kin / BK;
    LOAD_STAGE(0, 0);

    for (int kt = 0; kt < KT; kt++) {
        int cur = kt & 1;
        if (kt + 1 < KT) {
            LOAD_STAGE(cur ^ 1, (kt + 1) * BK);
            asm volatile("cp.async.wait_group 1;");
        } else {
            asm volatile("cp.async.wait_group 0;");
        }
        __syncthreads();

        #pragma unroll
        for (int kk = 0; kk < 2; kk++) {
            uint32_t afr[2][4];
            #pragma unroll
            for (int mt = 0; mt < 2; mt++) {
                int r = wm * 32 + mt * 16 + (lane & 15);
                int c = kk * 16 + (lane >> 4) * 8;
                uint32_t addr = smem_u32(&As[cur][r][c]);
                asm volatile(
                    "ldmatrix.sync.aligned.m8n8.x4.shared.b16 {%0,%1,%2,%3}, [%4];"
                    : "=r"(afr[mt][0]), "=r"(afr[mt][1]),
                      "=r"(afr[mt][2]), "=r"(afr[mt][3]) : "r"(addr));
            }
            uint32_t bfr[4][2];
            #pragma unroll
            for (int p = 0; p < 2; p++) {
                int r = kk * 16 + (lane & 15);
                int c = wn * 32 + p * 16 + (lane >> 4) * 8;
                uint32_t addr = smem_u32(&Bs[cur][r][c]);
                uint32_t r0, r1, r2, r3;
                asm volatile(
                    "ldmatrix.sync.aligned.m8n8.x4.trans.shared.b16 {%0,%1,%2,%3}, [%4];"
                    : "=r"(r0), "=r"(r1), "=r"(r2), "=r"(r3) : "r"(addr));
                bfr[p * 2][0] = r0;     bfr[p * 2][1] = r1;
                bfr[p * 2 + 1][0] = r2; bfr[p * 2 + 1][1] = r3;
            }
            #pragma unroll
            for (int mt = 0; mt < 2; mt++)
                #pragma unroll
                for (int nt = 0; nt < 4; nt++) {
                    asm volatile(
                        "mma.sync.aligned.m16n8k16.row.col.f32.f16.f16.f32 "
                        "{%0,%1,%2,%3}, {%4,%5,%6,%7}, {%8,%9}, {%0,%1,%2,%3};"
                        : "+f"(acc[mt][nt][0]), "+f"(acc[mt][nt][1]),
                          "+f"(acc[mt][nt][2]), "+f"(acc[mt][nt][3])
                        : "r"(afr[mt][0]), "r"(afr[mt][1]),
                          "r"(afr[mt][2]), "r"(afr[mt][3]),
                          "r"(bfr[nt][0]), "r"(bfr[nt][1]));
                }
        }
        __syncthreads();
    }
    #undef LOAD_STAGE

    int g = lane >> 2, t4 = lane & 3;
    float sp[2][2] = {}, tp[2][2] = {};
    #pragma unroll
    for (int mt = 0; mt < 2; mt++)
        #pragma unroll
        for (int nt = 0; nt < 4; nt++) {
            int cl = wn * 32 + nt * 8 + t4 * 2;
            int r  = row0 + wm * 32 + mt * 16;
            int c  = col0 + cl;
            __half2 lo = __floats2half2_rn(acc[mt][nt][0], acc[mt][nt][1]);
            __half2 hi = __floats2half2_rn(acc[mt][nt][2], acc[mt][nt][3]);
            *(__half2*)&C[(size_t)(r + g)     * Kout + c] = lo;
            *(__half2*)&C[(size_t)(r + g + 8) * Kout + c] = hi;
            float s0 = a_s[cl], s1 = a_s[cl + 1];
            float d0 = a_d[cl], d1 = a_d[cl + 1];
            sp[mt][0] += acc[mt][nt][0] * s0 + acc[mt][nt][1] * s1;
            sp[mt][1] += acc[mt][nt][2] * s0 + acc[mt][nt][3] * s1;
            tp[mt][0] += acc[mt][nt][0] * d0 + acc[mt][nt][1] * d1;
            tp[mt][1] += acc[mt][nt][2] * d0 + acc[mt][nt][3] * d1;
        }
    #pragma unroll
    for (int o = 1; o <= 2; o <<= 1)
        #pragma unroll
        for (int mt = 0; mt < 2; mt++) {
            sp[mt][0] += __shfl_xor_sync(0xffffffffu, sp[mt][0], o);
            sp[mt][1] += __shfl_xor_sync(0xffffffffu, sp[mt][1], o);
            tp[mt][0] += __shfl_xor_sync(0xffffffffu, tp[mt][0], o);
            tp[mt][1] += __shfl_xor_sync(0xffffffffu, tp[mt][1], o);
        }
    if (t4 == 0)
        #pragma unroll
        for (int mt = 0; mt < 2; mt++) {
            int r = wm * 32 + mt * 16 + g;
            s_sm[wn][r]     = sp[mt][0];  s_sm[wn][r + 8] = sp[mt][1];
            t_sm[wn][r]     = tp[mt][0];  t_sm[wn][r + 8] = tp[mt][1];
        }
    __syncthreads();
    if (tid < BM) {
        int r = row0 + tid;
        if (D == 64) {
            int h0 = col0 >> 6;                 // 0 or 2
            st[r * 8 + h0]         = s_sm[0][tid] + s_sm[1][tid];
            st[r * 8 + h0 + 1]     = s_sm[2][tid] + s_sm[3][tid];
            st[r * 8 + 4 + h0]     = t_sm[0][tid] + t_sm[1][tid];
            st[r * 8 + 4 + h0 + 1] = t_sm[2][tid] + t_sm[3][tid];
        } else {
            int h = col0 >> 7;                  // 0..3
            st[r * 8 + h]     = s_sm[0][tid] + s_sm[1][tid] + s_sm[2][tid] + s_sm[3][tid];
            st[r * 8 + 4 + h] = t_sm[0][tid] + t_sm[1][tid] + t_sm[2][tid] + t_sm[3][tid];
        }
    }
}

// ---------------------------------------------------------------------------
// Warp-per-(node,head) aggregation, concat layers (D=64, K=256).
// No block barriers: warp-private softmax + smem (j,w) strip + streamed
// gather (lane owns 2 channels -> 128B coalesced load per neighbor).
// ---------------------------------------------------------------------------
__global__ __launch_bounds__(256) void agg_concat(
    const __half* __restrict__ WhH, const float* __restrict__ st,
    __half* __restrict__ out)
{
    __shared__ float2 sjw[8][PAD];     // per-warp (w, j) list
    int wid  = threadIdx.x >> 5;
    int lane = threadIdx.x & 31;
    int gw = blockIdx.x * 8 + wid;
    int i = gw >> 2, h = gw & 3;

    int cnt = g_cnt[i];
    float ssrc = st[(size_t)i * 8 + h];

    float wreg[4];
    int   jreg[4];
    #pragma unroll
    for (int q = 0; q < 4; q++) {
        int k = q * 32 + lane;
        if (k < cnt) {
            int j = g_col_idx[i * PAD + k];
            jreg[q] = j;
            float z = ssrc + st[(size_t)j * 8 + 4 + h];
            wreg[q] = (z > 0.f) ? z : 0.2f * z;
        } else { jreg[q] = 0; wreg[q] = -CUDART_INF_F; }
    }
    float m = fmaxf(fmaxf(wreg[0], wreg[1]), fmaxf(wreg[2], wreg[3]));
    #pragma unroll
    for (int o = 16; o; o >>= 1) m = fmaxf(m, __shfl_xor_sync(0xffffffffu, m, o));
    float zsum = 0.f;
    #pragma unroll
    for (int q = 0; q < 4; q++) {
        float e = __expf(wreg[q] - m);       // exp(-inf)=0 for padding
        zsum += e;
        int k = q * 32 + lane;
        if (k < PAD) sjw[wid][k] = make_float2(e, __int_as_float(jreg[q]));
    }
    #pragma unroll
    for (int o = 16; o; o >>= 1) zsum += __shfl_xor_sync(0xffffffffu, zsum, o);
    __syncwarp();

    float ax = 0.f, ay = 0.f;
    const __half2* base = (const __half2*)(WhH + h * 64) + lane;
    const float2* jw = sjw[wid];
    #pragma unroll 4
    for (int k = 0; k < cnt; k++) {
        float2 p = jw[k];                     // broadcast LDS
        int j = __float_as_int(p.y);
        float2 v = __half22float2(base[(size_t)j * 128]);
        ax += p.x * v.x; ay += p.x * v.y;
    }
    float inv = 1.f / zsum;
    ax *= inv; ay *= inv;
    ax = (ax > 0.f) ? ax : (__expf(ax) - 1.f);
    ay = (ay > 0.f) ? ay : (__expf(ay) - 1.f);
    *(__half2*)&out[(size_t)i * 256 + h * 64 + 2 * lane] = __floats2half2_rn(ax, ay);
}

// ---------------------------------------------------------------------------
// Mean-layer aggregation (D=128, K=512). Block=128 (4 warps) per node;
// warp h handles head h (lane owns 4 channels); one barrier for head-mean.
// ---------------------------------------------------------------------------
__global__ __launch_bounds__(128) void agg_mean(
    const __half* __restrict__ WhH, const float* __restrict__ st,
    float* __restrict__ out)
{
    __shared__ float2 sjw[HEADS][PAD];
    __shared__ float  sacc[HEADS][128];
    int h    = threadIdx.x >> 5;
    int lane = threadIdx.x & 31;
    int i = blockIdx.x;

    int cnt = g_cnt[i];
    float ssrc = st[(size_t)i * 8 + h];

    float wreg[4];
    int   jreg[4];
    #pragma unroll
    for (int q = 0; q < 4; q++) {
        int k = q * 32 + lane;
        if (k < cnt) {
            int j = g_col_idx[i * PAD + k];
            jreg[q] = j;
            float z = ssrc + st[(size_t)j * 8 + 4 + h];
            wreg[q] = (z > 0.f) ? z : 0.2f * z;
        } else { jreg[q] = 0; wreg[q] = -CUDART_INF_F; }
    }
    float m = fmaxf(fmaxf(wreg[0], wreg[1]), fmaxf(wreg[2], wreg[3]));
    #pragma unroll
    for (int o = 16; o; o >>= 1) m = fmaxf(m, __shfl_xor_sync(0xffffffffu, m, o));
    float zsum = 0.f;
    #pragma unroll
    for (int q = 0; q < 4; q++) {
        float e = __expf(wreg[q] - m);
        zsum += e;
        int k = q * 32 + lane;
        if (k < PAD) sjw[h][k] = make_float2(e, __int_as_float(jreg[q]));
    }
    #pragma unroll
    for (int o = 16; o; o >>= 1) zsum += __shfl_xor_sync(0xffffffffu, zsum, o);
    __syncwarp();

    float a0 = 0.f, a1 = 0.f, a2 = 0.f, a3 = 0.f;
    const __half2* base = (const __half2*)(WhH + h * 128) + lane * 2;
    const float2* jw = sjw[h];
    #pragma unroll 4
    for (int k = 0; k < cnt; k++) {
        float2 p = jw[k];
        int j = __float_as_int(p.y);
        const __half2* row = base + (size_t)j * 256;
        float2 v0 = __half22float2(row[0]);
        float2 v1 = __half22float2(row[1]);
        a0 += p.x * v0.x; a1 += p.x * v0.y;
        a2 += p.x * v1.x; a3 += p.x * v1.y;
    }
    float inv = 1.f / zsum;
    sacc[h][lane * 4 + 0] = a0 * inv;
    sacc[h][lane * 4 + 1] = a1 * inv;
    sacc[h][lane * 4 + 2] = a2 * inv;
    sacc[h][lane * 4 + 3] = a3 * inv;
    __syncthreads();
    int c = threadIdx.x;
    out[(size_t)i * 128 + c] = 0.25f *
        (sacc[0][c] + sacc[1][c] + sacc[2][c] + sacc[3][c]);
}

// ---------------------------------------------------------------------------
extern "C" void kernel_launch(void* const* d_in, const int* in_sizes, int n_in,
                              void* d_out, int out_size)
{
    const float* x   = (const float*)d_in[0];
    const void*  adj =               d_in[1];
    const float* W0  = (const float*)d_in[2];
    const float* a0s = (const float*)d_in[3];
    const float* a0d = (const float*)d_in[4];
    const float* W1  = (const float*)d_in[5];
    const float* a1s = (const float*)d_in[6];
    const float* a1d = (const float*)d_in[7];
    const float* W2  = (const float*)d_in[8];
    const float* a2s = (const float*)d_in[9];
    const float* a2d = (const float*)d_in[10];
    float* out = (float*)d_out;

    __half *pxh, *pW0, *pW1, *pW2, *pWhH, *phH;
    float  *pst;
    cudaGetSymbolAddress((void**)&pxh,  g_xh);
    cudaGetSymbolAddress((void**)&pW0,  g_W0h);
    cudaGetSymbolAddress((void**)&pW1,  g_W1h);
    cudaGetSymbolAddress((void**)&pW2,  g_W2h);
    cudaGetSymbolAddress((void**)&pWhH, g_WhH);
    cudaGetSymbolAddress((void**)&phH,  g_hH);
    cudaGetSymbolAddress((void**)&pst,  g_st);

    static cudaStream_t sB = 0;
    static cudaEvent_t  eFork = 0, eJoin = 0;
    if (!sB) {
        cudaStreamCreateWithFlags(&sB, cudaStreamNonBlocking);
        cudaEventCreateWithFlags(&eFork, cudaEventDisableTiming);
        cudaEventCreateWithFlags(&eJoin, cudaEventDisableTiming);
    }

    cudaEventRecord(eFork, 0);
    cudaStreamWaitEvent(sB, eFork, 0);

    prep<<<2048, 256, 0, sB>>>(x, W0, W1, W2, pxh, pW0, pW1, pW2);
    gemm_fused<<<dim3(2, GN / BM), 256, 0, sB>>>(pxh, pW0, pWhH, a0s, a0d,
                                                 pst, 256, 256, 64);
    cudaEventRecord(eJoin, sB);

    detect_kernel<<<1, 256>>>((const unsigned char*)adj);
    csr_build<<<GN / 8, 256>>>(adj);
    cudaStreamWaitEvent(0, eJoin, 0);

    agg_concat<<<GN * HEADS / 8, 256>>>(pWhH, pst, phH);

    gemm_fused<<<dim3(2, GN / BM), 256>>>(phH, pW1, pWhH, a1s, a1d,
                                          pst, 256, 256, 64);
    agg_concat<<<GN * HEADS / 8, 256>>>(pWhH, pst, phH);

    gemm_fused<<<dim3(4, GN / BM), 256>>>(phH, pW2, pWhH, a2s, a2d,
                                          pst, 256, 512, 128);
    agg_mean<<<GN, 128>>>(pWhH, pst, out);
}